// round 1
// baseline (speedup 1.0000x reference)
#include <cuda_runtime.h>

// Problem constants
#define B_  4
#define C_  84
#define CP_ 80        // channels used for the max (points[:, :-4])
#define H_  512
#define W_  512
#define HW_ (H_ * W_)        // 262144
#define W4_ (W_ / 4)         // 128
#define HW4_ (HW_ / 4)       // 65536

// 4 MB scratch for probs = max over first 80 channels
__device__ float g_probs[B_ * HW_];

// ---------------------------------------------------------------------------
// Kernel 1: probs[b,h,w] = max_{c<80} points[b,c,h,w]   (float4 vectorized)
// ---------------------------------------------------------------------------
__global__ __launch_bounds__(256) void probs_kernel(const float* __restrict__ pts) {
    int t = blockIdx.x * blockDim.x + threadIdx.x;      // 0 .. B*HW/4
    if (t >= B_ * HW4_) return;
    int b   = t / HW4_;
    int hw4 = t - b * HW4_;

    const float4* base = reinterpret_cast<const float4*>(pts)
                       + (size_t)b * C_ * HW4_ + hw4;

    float4 m = base[0];
    #pragma unroll 8
    for (int c = 1; c < CP_; c++) {
        float4 v = base[(size_t)c * HW4_];
        m.x = fmaxf(m.x, v.x);
        m.y = fmaxf(m.y, v.y);
        m.z = fmaxf(m.z, v.z);
        m.w = fmaxf(m.w, v.w);
    }
    reinterpret_cast<float4*>(g_probs)[(size_t)b * HW4_ + hw4] = m;
}

// Load 6 consecutive probs values of row r: columns [w0-1 .. w0+4], 0 for OOB.
__device__ __forceinline__ void load_row6(const float* __restrict__ pr,
                                          int r, int w0, float a[6]) {
    if (r < 0 || r >= H_) {
        #pragma unroll
        for (int k = 0; k < 6; k++) a[k] = 0.0f;
        return;
    }
    const float* row = pr + (size_t)r * W_;
    float4 v = *reinterpret_cast<const float4*>(row + w0);
    a[1] = v.x; a[2] = v.y; a[3] = v.z; a[4] = v.w;
    a[0] = (w0 > 0)       ? row[w0 - 1] : 0.0f;
    a[5] = (w0 + 4 < W_)  ? row[w0 + 4] : 0.0f;
}

// ---------------------------------------------------------------------------
// Kernel 2: compute 3x3 NMS mask from g_probs, multiply all 84 channels.
// One thread per (b, h, w/4). probs reads hit L2 (4 MB total).
// Mask rule (center idx = 4): strict > for offsets (-1,*) and (0,-1);
// >= for (0,+1) and (+1,*). OOB neighbors are 0 (zero padding).
// ---------------------------------------------------------------------------
__global__ __launch_bounds__(256) void nms_mul_kernel(const float* __restrict__ pts,
                                                      float* __restrict__ out) {
    int t = blockIdx.x * blockDim.x + threadIdx.x;      // 0 .. B*H*W4
    if (t >= B_ * H_ * W4_) return;
    int b   = t / (H_ * W4_);
    int rem = t - b * (H_ * W4_);
    int i   = rem / W4_;
    int j4  = rem - i * W4_;
    int w0  = j4 * 4;

    const float* pr = g_probs + (size_t)b * HW_;

    float up[6], mid[6], dn[6];
    load_row6(pr, i - 1, w0, up);
    load_row6(pr, i,     w0, mid);
    load_row6(pr, i + 1, w0, dn);

    float m[4];
    #pragma unroll
    for (int k = 0; k < 4; k++) {
        float p = mid[k + 1];
        bool ok =  (p >  up[k])     & (p >  up[k + 1]) & (p >  up[k + 2])
                 & (p >  mid[k])    & (p >= mid[k + 2])
                 & (p >= dn[k])     & (p >= dn[k + 1]) & (p >= dn[k + 2]);
        m[k] = ok ? 1.0f : 0.0f;
    }

    size_t pos = (size_t)(b * C_) * HW4_ + (size_t)i * W4_ + j4;
    const float4* src = reinterpret_cast<const float4*>(pts) + pos;
    float4*       dst = reinterpret_cast<float4*>(out) + pos;

    #pragma unroll 4
    for (int c = 0; c < C_; c++) {
        float4 v = src[(size_t)c * HW4_];
        v.x *= m[0];
        v.y *= m[1];
        v.z *= m[2];
        v.w *= m[3];
        dst[(size_t)c * HW4_] = v;
    }
}

extern "C" void kernel_launch(void* const* d_in, const int* in_sizes, int n_in,
                              void* d_out, int out_size) {
    const float* pts = (const float*)d_in[0];
    float* out = (float*)d_out;

    int n1 = B_ * HW4_;           // 262144 threads
    probs_kernel<<<(n1 + 255) / 256, 256>>>(pts);

    int n2 = B_ * H_ * W4_;       // 262144 threads
    nms_mul_kernel<<<(n2 + 255) / 256, 256>>>(pts, out);
}